// round 14
// baseline (speedup 1.0000x reference)
#include <cuda_runtime.h>
#include <cstdint>

// Problem constants
#define B_      16
#define C_      64
#define HW_     65536      // 256*256

// Radix sort: 4 stable LSD passes of 8 bits over the 32-bit ordered-float
// value (high half of a u64 key). Low bits: channel<<16 | spatial(16).
// Keys generated in spatial order; stability => jnp argsort tie order.
#define THREADS 256
#define NW      8
#define IPT     4
#define TSIZE   1024               // items per tile (THREADS * IPT)
#define NBLK    64                 // tiles per batch
#define TPB     2                  // tiles per scatter block
#define SGRID   (B_ * NBLK / TPB)  // 512 scatter blocks -> ONE wave at occ 6
#define RSIZE   (B_ * NBLK * 256)  // 262144 entries per hist region

__device__ __align__(16) unsigned long long g_kv0[B_ * HW_];
__device__ __align__(16) unsigned long long g_kv1[B_ * HW_];
// 4 rotating RAW histogram regions, layout (batch, tile, bin) -- bin
// fastest so fused-scan reads are coalesced. Producers: ck->R0, s0->R1,
// s1->R2, s2->R3. Readers: s_p -> R_p. Zeroing: s0->R3, s1->R0, s2->R1,
// s3->R2 (each region zeroed after its reader, before its next producer).
__device__ __align__(16) unsigned int g_hist[4][RSIZE];

__device__ __forceinline__ unsigned int f2ord(float f) {
    unsigned int u = __float_as_uint(f);
    return (u & 0x80000000u) ? ~u : (u | 0x80000000u);
}

// -------------------------------------------------------------------------
// Kernel 1: channel max + argmax (first occurrence), emit u64 keys AND
// accumulate the pass-0 raw histogram into g_hist[0]. Channel axis split
// 4-ways across lanes; shfl_xor(1),(2) combine. grid = 4096 x 256.
// -------------------------------------------------------------------------
__global__ void compute_keys_kernel(const float* __restrict__ x) {
    __shared__ unsigned int h[256];
    h[threadIdx.x] = 0;
    __syncthreads();

    int gid   = blockIdx.x * 256 + threadIdx.x;   // 0 .. 1048575
    int chunk = gid & 3;                          // channel chunk (16 ch each)
    int qg    = gid >> 2;                         // global pixel-group
    int batch = qg >> 14;
    int q     = qg & 16383;

    const float4* xb = reinterpret_cast<const float4*>(x)
                       + (size_t)batch * (C_ * (HW_ / 4))
                       + (size_t)(chunk * 16) * (HW_ / 4) + q;

    float4 best = xb[0];
    int c0 = 0, c1 = 0, c2 = 0, c3 = 0;
    #pragma unroll
    for (int c = 1; c < 16; ++c) {
        float4 v = xb[(size_t)c * (HW_ / 4)];
        if (v.x > best.x) { best.x = v.x; c0 = c; }
        if (v.y > best.y) { best.y = v.y; c1 = c; }
        if (v.z > best.z) { best.z = v.z; c2 = c; }
        if (v.w > best.w) { best.w = v.w; c3 = c; }
    }
    int cb = chunk * 16;
    c0 += cb; c1 += cb; c2 += cb; c3 += cb;

    // Cross-chunk combine; equal value -> smaller channel = first occurrence.
    #pragma unroll
    for (int m = 1; m <= 2; m <<= 1) {
        float ox = __shfl_xor_sync(0xffffffffu, best.x, m);
        float oy = __shfl_xor_sync(0xffffffffu, best.y, m);
        float oz = __shfl_xor_sync(0xffffffffu, best.z, m);
        float ow = __shfl_xor_sync(0xffffffffu, best.w, m);
        int   o0 = __shfl_xor_sync(0xffffffffu, c0, m);
        int   o1 = __shfl_xor_sync(0xffffffffu, c1, m);
        int   o2 = __shfl_xor_sync(0xffffffffu, c2, m);
        int   o3 = __shfl_xor_sync(0xffffffffu, c3, m);
        if (ox > best.x || (ox == best.x && o0 < c0)) { best.x = ox; c0 = o0; }
        if (oy > best.y || (oy == best.y && o1 < c1)) { best.y = oy; c1 = o1; }
        if (oz > best.z || (oz == best.z && o2 < c2)) { best.z = oz; c2 = o2; }
        if (ow > best.w || (ow == best.w && o3 < c3)) { best.w = ow; c3 = o3; }
    }

    if (chunk == 0) {
        unsigned int e0 = f2ord(best.x), e1 = f2ord(best.y);
        unsigned int e2 = f2ord(best.z), e3 = f2ord(best.w);
        size_t o = (size_t)batch * HW_;
        unsigned int s = (unsigned int)q * 4u;
        ulonglong2 k01, k23;
        k01.x = ((unsigned long long)e0 << 32) | ((unsigned)c0 << 16) | (s + 0u);
        k01.y = ((unsigned long long)e1 << 32) | ((unsigned)c1 << 16) | (s + 1u);
        k23.x = ((unsigned long long)e2 << 32) | ((unsigned)c2 << 16) | (s + 2u);
        k23.y = ((unsigned long long)e3 << 32) | ((unsigned)c3 << 16) | (s + 3u);
        *reinterpret_cast<ulonglong2*>(g_kv0 + o + s)     = k01;
        *reinterpret_cast<ulonglong2*>(g_kv0 + o + s + 2) = k23;

        atomicAdd(&h[e0 & 255u], 1u);
        atomicAdd(&h[e1 & 255u], 1u);
        atomicAdd(&h[e2 & 255u], 1u);
        atomicAdd(&h[e3 & 255u], 1u);
    }
    __syncthreads();

    int tile    = (blockIdx.x & 255) >> 2;       // dest tile in batch
    int batch_b = blockIdx.x >> 8;
    unsigned int cnt = h[threadIdx.x];
    if (cnt)
        atomicAdd(&g_hist[0][((size_t)batch_b * NBLK + tile) * 256 + threadIdx.x], cnt);
}

// -------------------------------------------------------------------------
// Kernel 2: stable scatter, 2 tiles per block (single wave at occ 6),
// fused coalesced histogram scan done ONCE covering both tiles.
// grid = 512 x 256.
// -------------------------------------------------------------------------
template <int SHIFT, int RIN, int ROUT, int RZERO, bool LAST>
__global__ void __launch_bounds__(THREADS, 6)
scatter_kernel(float4* __restrict__ outv) {
    __shared__ unsigned int       wh[NW][256];
    __shared__ unsigned long long s_kv[TSIZE];
    __shared__ unsigned int       dstart[256];
    __shared__ unsigned int       gbase[256];
    __shared__ unsigned int       sw[NW];
    __shared__ unsigned int       sw2[NW];

    const unsigned long long* __restrict__ in_kv  = (RIN & 1) ? g_kv1 : g_kv0;
    unsigned long long*       __restrict__ out_kv = (RIN & 1) ? g_kv0 : g_kv1;

    int tid = threadIdx.x;
    int w = tid >> 5, lane = tid & 31;
    unsigned int lt = (1u << lane) - 1u;

    int blk = blockIdx.x, batch = blk >> 5, lpair = blk & 31;
    int tile0 = lpair * 2;

    // Zero this block's two tile-slices of the rotation region.
    g_hist[RZERO][(size_t)blk * 512 + tid]       = 0u;
    g_hist[RZERO][(size_t)blk * 512 + 256 + tid] = 0u;

    // Fused hist scan (coalesced), once for both tiles. bin = tid.
    const unsigned int* hb = g_hist[RIN] + (size_t)batch * (NBLK * 256) + tid;
    unsigned int lpre0 = 0, bintot = 0, hv_t0 = 0;
    #pragma unroll 8
    for (int j = 0; j < NBLK; ++j) {
        unsigned int hv = hb[j * 256];
        bintot += hv;
        if (j < tile0)  lpre0 += hv;
        if (j == tile0) hv_t0 = hv;
    }
    unsigned int lpre1 = lpre0 + hv_t0;

    // Block-wide exclusive scan of bintot -> batch-global bin base.
    unsigned int binBase;
    {
        unsigned int inc2 = bintot;
        #pragma unroll
        for (int o = 1; o < 32; o <<= 1) {
            unsigned int t2 = __shfl_up_sync(0xffffffffu, inc2, o);
            if (lane >= o) inc2 += t2;
        }
        if (lane == 31) sw2[w] = inc2;
        __syncthreads();
        if (tid == 0) {
            unsigned int r2 = 0;
            #pragma unroll
            for (int q = 0; q < NW; ++q) { unsigned int t2 = sw2[q]; sw2[q] = r2; r2 += t2; }
        }
        __syncthreads();
        binBase = inc2 - bintot + sw2[w];
    }

    size_t obase = (size_t)batch * HW_;

    #pragma unroll
    for (int t = 0; t < TPB; ++t) {
        int tile = tile0 + t;
        unsigned int lpre = t ? lpre1 : lpre0;
        size_t base = (size_t)(batch * NBLK + tile) * TSIZE + (size_t)w * (32 * IPT);

        for (int j = tid; j < NW * 256; j += THREADS)
            (&wh[0][0])[j] = 0;
        __syncthreads();

        unsigned long long kv[IPT];
        unsigned int d[IPT];
        unsigned int rank[IPT];

        #pragma unroll
        for (int i = 0; i < IPT; ++i) {
            kv[i] = in_kv[base + i * 32 + lane];
            d[i] = (unsigned)(kv[i] >> (32 + SHIFT)) & 255u;
            rank[i] = 0;
        }

        // Streaming-ballot ranking (per-warp, stable).
        #pragma unroll
        for (int j = 0; j < IPT; ++j) {
            unsigned int bal[8];
            #pragma unroll
            for (int b = 0; b < 8; ++b)
                bal[b] = __ballot_sync(0xffffffffu, (d[j] >> b) & 1u);
            #pragma unroll
            for (int i = j; i < IPT; ++i) {
                unsigned int m = 0xffffffffu;
                #pragma unroll
                for (int b = 0; b < 8; ++b)
                    m &= bal[b] ^ (((d[i] >> b) & 1u) - 1u);
                if (i == j) {
                    unsigned int rw = __popc(m & lt);
                    rank[i] += rw;
                    if (rw == 0)
                        atomicAdd(&wh[w][d[i]], __popc(m));
                } else {
                    rank[i] += __popc(m);
                }
            }
        }
        __syncthreads();

        // Per-bin cross-warp scan of own-tile counts (bin = tid).
        unsigned int running = 0;
        #pragma unroll
        for (int q = 0; q < NW; ++q) {
            unsigned int tc = wh[q][tid];
            wh[q][tid] = running;
            running += tc;
        }

        // Block-wide exclusive scan of in-tile digit totals.
        unsigned int inc1 = running;
        #pragma unroll
        for (int o = 1; o < 32; o <<= 1) {
            unsigned int t1 = __shfl_up_sync(0xffffffffu, inc1, o);
            if (lane >= o) inc1 += t1;
        }
        if (lane == 31) sw[w] = inc1;
        __syncthreads();
        if (tid == 0) {
            unsigned int r1 = 0;
            #pragma unroll
            for (int q = 0; q < NW; ++q) { unsigned int t1 = sw[q]; sw[q] = r1; r1 += t1; }
        }
        __syncthreads();
        unsigned int excl = inc1 - running + sw[w];
        dstart[tid] = excl;
        gbase[tid]  = binBase + lpre - excl;
        __syncthreads();

        // Exchange into tile-digit-sorted order.
        #pragma unroll
        for (int i = 0; i < IPT; ++i) {
            unsigned int p = dstart[d[i]] + wh[w][d[i]] + rank[i];
            s_kv[p] = kv[i];
        }
        __syncthreads();

        // Coalesced write-out; global pos = gbase[digit] + p.
        #pragma unroll
        for (int j = 0; j < IPT; ++j) {
            unsigned int p = (unsigned int)tid + j * THREADS;
            unsigned long long k = s_kv[p];
            unsigned int dd = (unsigned)(k >> (32 + SHIFT)) & 255u;
            unsigned int pos = gbase[dd] + p;
            if (!LAST) {
                out_kv[obase + pos] = k;
                unsigned int d2 = (unsigned)(k >> (40 + SHIFT)) & 255u;
                atomicAdd(&g_hist[ROUT][((size_t)batch * NBLK + (pos >> 10)) * 256 + d2], 1u);
            } else {
                unsigned int hi = (unsigned int)(k >> 32);
                unsigned int u  = (hi & 0x80000000u) ? (hi ^ 0x80000000u) : ~hi;
                unsigned int lo = (unsigned int)k & 0x3FFFFFu;   // c<<16|s == flat idx
                unsigned int s  = lo & 0xFFFFu;
                float4 o;
                o.x = __uint_as_float(u);
                o.y = (float)lo;                      // c*65536 + s, < 2^22, exact
                o.z = (float)(s >> 8);                // row (W=256)
                o.w = (float)(s & 255u);              // col
                outv[obase + pos] = o;
            }
        }
        if (t + 1 < TPB) __syncthreads();
    }
}

// -------------------------------------------------------------------------
extern "C" void kernel_launch(void* const* d_in, const int* in_sizes, int n_in,
                              void* d_out, int out_size) {
    const float* x = (const float*)d_in[0];
    float4* out = (float4*)d_out;

    compute_keys_kernel<<<4096, 256>>>(x);                         // keys + hist -> R0
    scatter_kernel< 0, 0, 1, 3, false><<<SGRID, THREADS>>>(nullptr); // kv0->kv1
    scatter_kernel< 8, 1, 2, 0, false><<<SGRID, THREADS>>>(nullptr); // kv1->kv0
    scatter_kernel<16, 2, 3, 1, false><<<SGRID, THREADS>>>(nullptr); // kv0->kv1
    scatter_kernel<24, 3, 0, 2, true ><<<SGRID, THREADS>>>(out);     // kv1->d_out
}